// round 12
// baseline (speedup 1.0000x reference)
#include <cuda_runtime.h>
#include <cuda_bf16.h>
#include <cstdint>
#include <math.h>

#define B_ 4
#define H_ 8
#define T_ 8192
#define D_ 64
#define C_ 64
#define W_ 128
#define BH_ (B_*H_)

// ---------------- scratch ----------------
__device__ float g_dists[(size_t)BH_ * C_ * T_];   // [bh][c][t]
__device__ int   g_idx[BH_ * C_ * W_];
__device__ float g_den[BH_ * T_];
__device__ float g_loss;

__device__ __forceinline__ uint32_t packbf(__nv_bfloat16 a, __nv_bfloat16 b) {
    return ((uint32_t)__bfloat16_as_ushort(b) << 16) | (uint32_t)__bfloat16_as_ushort(a);
}
__device__ __forceinline__ void split2(float x, float y, uint32_t& hi, uint32_t& lo) {
    __nv_bfloat16 hx = __float2bfloat16_rn(x), hy = __float2bfloat16_rn(y);
    hi = packbf(hx, hy);
    lo = packbf(__float2bfloat16_rn(x - __bfloat162float(hx)),
                __float2bfloat16_rn(y - __bfloat162float(hy)));
}
__device__ __forceinline__ void mma_bf16(float (&c)[4], const uint32_t (&a)[4],
                                         uint32_t b0, uint32_t b1) {
    asm volatile("mma.sync.aligned.m16n8k16.row.col.f32.bf16.bf16.f32 "
        "{%0,%1,%2,%3}, {%4,%5,%6,%7}, {%8,%9}, {%0,%1,%2,%3};"
        : "+f"(c[0]), "+f"(c[1]), "+f"(c[2]), "+f"(c[3])
        : "r"(a[0]), "r"(a[1]), "r"(a[2]), "r"(a[3]), "r"(b0), "r"(b1));
}
__device__ __forceinline__ void ldsm4(uint32_t (&r)[4], uint32_t addr) {
    asm volatile("ldmatrix.sync.aligned.m8n8.x4.shared.b16 {%0,%1,%2,%3}, [%4];"
        : "=r"(r[0]), "=r"(r[1]), "=r"(r[2]), "=r"(r[3]) : "r"(addr));
}
__device__ __forceinline__ void ldsm4t(uint32_t (&r)[4], uint32_t addr) {
    asm volatile("ldmatrix.sync.aligned.m8n8.x4.trans.shared.b16 {%0,%1,%2,%3}, [%4];"
        : "=r"(r[0]), "=r"(r[1]), "=r"(r[2]), "=r"(r[3]) : "r"(addr));
}
__device__ __forceinline__ uint32_t smem_u32(const void* p) {
    uint32_t a;
    asm("{ .reg .u64 t; cvta.to.shared.u64 t, %1; cvt.u32.u64 %0, t; }" : "=r"(a) : "l"(p));
    return a;
}

// ---------------- zero den/loss ----------------
__global__ void k_zero() {
    int i = blockIdx.x * blockDim.x + threadIdx.x;
    if (i < BH_ * T_) g_den[i] = 0.f;
    if (i == 0) g_loss = 0.f;
}

// ---------------- dists = l2norm(qk) . means, fused commitment loss ----------------
__global__ void __launch_bounds__(256) k_dists(const float* __restrict__ qk,
                                               const float* __restrict__ means) {
    __shared__ float sQ[64 * 65];
    __shared__ float sM[64 * 65];
    __shared__ float sInv[64];
    int bh = blockIdx.y;
    int h = bh & (H_ - 1);
    int t0 = blockIdx.x * 64;
    const float* qp = qk + ((size_t)bh * T_ + t0) * D_;
    const float* mp = means + (size_t)h * C_ * D_;
    int tid = threadIdx.x;

    for (int i = tid; i < 64 * 16; i += 256) {
        int r = i >> 4, c4 = (i & 15) << 2;
        float4 a = *(const float4*)(qp + r * D_ + c4);
        sQ[r * 65 + c4 + 0] = a.x; sQ[r * 65 + c4 + 1] = a.y;
        sQ[r * 65 + c4 + 2] = a.z; sQ[r * 65 + c4 + 3] = a.w;
        float4 m = *(const float4*)(mp + r * D_ + c4);
        sM[r * 65 + c4 + 0] = m.x; sM[r * 65 + c4 + 1] = m.y;
        sM[r * 65 + c4 + 2] = m.z; sM[r * 65 + c4 + 3] = m.w;
    }
    __syncthreads();
    if (tid < 64) {
        float s = 0.f;
        #pragma unroll
        for (int k = 0; k < 64; k++) { float x = sQ[tid * 65 + k]; s += x * x; }
        sInv[tid] = 1.f / fmaxf(sqrtf(s), 1e-12f);
    }
    __syncthreads();

    int ty = tid >> 4, tx = tid & 15;
    float acc[4][4];
    #pragma unroll
    for (int u = 0; u < 4; u++)
        #pragma unroll
        for (int w = 0; w < 4; w++) acc[u][w] = 0.f;

    for (int k = 0; k < 64; k++) {
        float a[4], b[4];
        #pragma unroll
        for (int u = 0; u < 4; u++) a[u] = sQ[(ty * 4 + u) * 65 + k];
        #pragma unroll
        for (int w = 0; w < 4; w++) b[w] = sM[(tx * 4 + w) * 65 + k];
        #pragma unroll
        for (int u = 0; u < 4; u++)
            #pragma unroll
            for (int w = 0; w < 4; w++) acc[u][w] += a[u] * b[w];
    }
    __syncthreads();
    #pragma unroll
    for (int u = 0; u < 4; u++)
        #pragma unroll
        for (int w = 0; w < 4; w++)
            sQ[(tx * 4 + w) * 65 + (ty * 4 + u)] = acc[u][w] * sInv[ty * 4 + u];
    __syncthreads();
    float* dst = &g_dists[((size_t)bh * C_) * T_ + t0];
    for (int i = tid; i < 4096; i += 256) {
        int c = i >> 6, r = i & 63;
        dst[(size_t)c * T_ + r] = sQ[c * 65 + r];
    }
    if (tid < 64) {
        float m = -1e30f;
        #pragma unroll 8
        for (int c = 0; c < 64; c++) m = fmaxf(m, sQ[c * 65 + tid]);
        float v = 2.f - 2.f * m;
        #pragma unroll
        for (int off = 16; off > 0; off >>= 1) v += __shfl_down_sync(0xFFFFFFFFu, v, off);
        if ((tid & 31) == 0) atomicAdd(&g_loss, v);
    }
}

// ---------------- exact top-128: two-pass 2048-bin radix ----------------
__device__ __forceinline__ unsigned kmap(float f) {
    unsigned u = __float_as_uint(f);
    return (u & 0x80000000u) ? ~u : (u | 0x80000000u);
}
__global__ void __launch_bounds__(512, 2) k_topk() {
    int row = blockIdx.x;
    const float* dp = g_dists + (size_t)row * T_;
    int tid = threadIdx.x;
    __shared__ int hist[2048];
    __shared__ int wsum[16];
    __shared__ int sSel, sNgt, sCntG, sCntC;
    __shared__ int sIdx[128];
    __shared__ unsigned long long cand[256];

    #pragma unroll
    for (int j = 0; j < 4; j++) hist[tid + j * 512] = 0;
    if (tid == 0) { sCntG = 0; sCntC = 0; }
    __syncthreads();

    #pragma unroll
    for (int k = 0; k < 16; k++) {
        unsigned key = kmap(dp[tid + (k << 9)]);
        atomicAdd(&hist[key >> 21], 1);
    }
    __syncthreads();

    int h0 = hist[4 * tid], h1 = hist[4 * tid + 1], h2 = hist[4 * tid + 2], h3 = hist[4 * tid + 3];
    int s = h0 + h1 + h2 + h3;
    int lane = tid & 31, wid = tid >> 5;
    int suf = s;
    #pragma unroll
    for (int off = 1; off < 32; off <<= 1) {
        int t = __shfl_down_sync(0xFFFFFFFFu, suf, off);
        if (lane + off < 32) suf += t;
    }
    if (lane == 0) wsum[wid] = suf;
    __syncthreads();
    if (tid < 16) {
        int v = wsum[tid];
        int sw = v;
        #pragma unroll
        for (int off = 1; off < 16; off <<= 1) {
            int t = __shfl_down_sync(0xFFFFu, sw, off);
            if (tid + off < 16) sw += t;
        }
        wsum[tid] = sw - v;
    }
    __syncthreads();
    int tailT = wsum[wid] + (suf - s);
    int suf3 = tailT + h3;
    int suf2 = suf3 + h2;
    int suf1 = suf2 + h1;
    int suf0 = suf1 + h0;
    if (suf0 >= 128 && suf1 < 128) { sSel = 4 * tid;     sNgt = suf1; }
    if (suf1 >= 128 && suf2 < 128) { sSel = 4 * tid + 1; sNgt = suf2; }
    if (suf2 >= 128 && suf3 < 128) { sSel = 4 * tid + 2; sNgt = suf3; }
    if (suf3 >= 128 && tailT < 128){ sSel = 4 * tid + 3; sNgt = tailT; }
    __syncthreads();
    unsigned selBin = (unsigned)sSel;
    int ngt = sNgt;

    #pragma unroll
    for (int k = 0; k < 16; k++) {
        unsigned key = kmap(dp[tid + (k << 9)]);
        unsigned b = key >> 21;
        if (b > selBin) {
            int p = atomicAdd(&sCntG, 1);
            sIdx[p] = tid + (k << 9);
        } else if (b == selBin) {
            int p = atomicAdd(&sCntC, 1);
            if (p < 256)
                cand[p] = ((unsigned long long)(~key) << 32) | (unsigned)(tid + (k << 9));
        }
    }
    __syncthreads();
    int cn = sCntC < 256 ? sCntC : 256;
    int need = 128 - ngt;
    for (int i = tid; i < 256; i += 512) if (i >= cn) cand[i] = 0xFFFFFFFFFFFFFFFFull;
    __syncthreads();
    for (int sz = 2; sz <= 256; sz <<= 1) {
        for (int st = sz >> 1; st > 0; st >>= 1) {
            if (tid < 256) {
                int i = tid, j = i ^ st;
                if (j > i) {
                    unsigned long long a = cand[i], b = cand[j];
                    bool up = ((i & sz) == 0);
                    if ((a > b) == up) { cand[i] = b; cand[j] = a; }
                }
            }
            __syncthreads();
        }
    }
    if (tid < need) sIdx[ngt + tid] = (int)(cand[tid] & 0xFFFFFFFFu);
    __syncthreads();
    for (int sz = 2; sz <= 128; sz <<= 1) {
        for (int st = sz >> 1; st > 0; st >>= 1) {
            if (tid < 128) {
                int i = tid, ixj = i ^ st;
                if (ixj > i) {
                    int a = sIdx[i], b2 = sIdx[ixj];
                    bool up = ((i & sz) == 0);
                    if ((a > b2) == up) { sIdx[i] = b2; sIdx[ixj] = a; }
                }
            }
            __syncthreads();
        }
    }
    if (tid < 128) g_idx[row * W_ + tid] = sIdx[tid];
}

// ---------------- fused gather + HMMA attention + scatter (1024 threads) ----------------
#define OFF_AHI   0u
#define OFF_ALO   18432u
#define OFF_R     36864u
#define OFF_VHI   55296u
#define OFF_VLO   73728u
#define OFF_D     92160u
#define OFF_INV   159744u
#define OFF_IDXS  160256u
#define SMEM_ATTN_BYTES 160768u
// sRel (bf16 [128][136] = 34816B) overlays AHI+ALO after GEMM2's k-loop
#define OFF_RELS  OFF_AHI

#define STR_BF 72
#define STR_D  132
#define NT_ATTN 1024

__global__ void __launch_bounds__(NT_ATTN)
k_attn(const float* __restrict__ qk,
       const float* __restrict__ vv,
       const float* __restrict__ relw,
       float* __restrict__ outNum) {
    extern __shared__ char sm[];
    float* sD   = (float*)(sm + OFF_D);
    float* sInv = (float*)(sm + OFF_INV);
    int*   sIdx = (int*)(sm + OFF_IDXS);
    uint32_t sbase = smem_u32(sm);

    int bhc = blockIdx.x;
    int bh = bhc >> 6;
    int h = bh & (H_ - 1);
    int tid = threadIdx.x;

    if (tid < 128) sIdx[tid] = g_idx[bhc * W_ + tid];
    __syncthreads();

    // ---- fused gather: q->A hi/lo + norms; v->V hi/lo; rel->R ----
    for (int i = tid; i < 128 * 16; i += NT_ATTN) {
        int r = i >> 4, c4 = (i & 15) << 2;
        int tok = sIdx[r];
        uint32_t off = (uint32_t)(r * STR_BF + c4) * 2;
        uint32_t hi0, lo0, hi1, lo1;

        float4 q4 = *(const float4*)(qk + ((size_t)bh * T_ + tok) * D_ + c4);
        split2(q4.x, q4.y, hi0, lo0);
        split2(q4.z, q4.w, hi1, lo1);
        *(uint32_t*)(sm + OFF_AHI + off)     = hi0;
        *(uint32_t*)(sm + OFF_AHI + off + 4) = hi1;
        *(uint32_t*)(sm + OFF_ALO + off)     = lo0;
        *(uint32_t*)(sm + OFF_ALO + off + 4) = lo1;
        float s = q4.x * q4.x + q4.y * q4.y + q4.z * q4.z + q4.w * q4.w;
        s += __shfl_xor_sync(0xFFFFFFFFu, s, 1);
        s += __shfl_xor_sync(0xFFFFFFFFu, s, 2);
        s += __shfl_xor_sync(0xFFFFFFFFu, s, 4);
        s += __shfl_xor_sync(0xFFFFFFFFu, s, 8);
        if ((tid & 15) == 0) sInv[r] = 1.f / fmaxf(sqrtf(s), 1e-12f);

        float4 v4 = *(const float4*)(vv + ((size_t)bh * T_ + tok) * D_ + c4);
        split2(v4.x, v4.y, hi0, lo0);
        split2(v4.z, v4.w, hi1, lo1);
        *(uint32_t*)(sm + OFF_VHI + off)     = hi0;
        *(uint32_t*)(sm + OFF_VHI + off + 4) = hi1;
        *(uint32_t*)(sm + OFF_VLO + off)     = lo0;
        *(uint32_t*)(sm + OFF_VLO + off + 4) = lo1;

        float4 r4 = *(const float4*)(relw + ((size_t)r * H_ + h) * D_ + c4);
        *(uint32_t*)(sm + OFF_R + off)     = packbf(__float2bfloat16_rn(r4.x), __float2bfloat16_rn(r4.y));
        *(uint32_t*)(sm + OFF_R + off + 4) = packbf(__float2bfloat16_rn(r4.z), __float2bfloat16_rn(r4.w));
    }
    __syncthreads();

    const int lane = tid & 31, warp = tid >> 5;
    const int qr = lane >> 2, qc = (lane & 3) << 1;
    const float scale = 0.125f;

    const int aKof = (lane >> 4) << 3;
    const int aRowL = lane & 15;
    const int bRowOf = ((lane >> 4) << 3) + (lane & 7);
    const int bKof = ((lane >> 3) & 1) << 3;

    const int R0 = (warp & 7) << 4;      // 8 row blocks of 16
    const int C0 = (warp >> 3) << 5;     // 4 col blocks of 32

    // ---- GEMM1: dots (3-term split), warp = 16 rows x 32 cols ----
    {
        float acc[4][4];
        #pragma unroll
        for (int nt = 0; nt < 4; nt++)
            #pragma unroll
            for (int u = 0; u < 4; u++) acc[nt][u] = 0.f;

        #pragma unroll
        for (int kt = 0; kt < 4; kt++) {
            int ka = kt * 16;
            uint32_t ah[4], al[4];
            uint32_t aAddr = sbase + OFF_AHI + (uint32_t)((R0 + aRowL) * STR_BF + ka + aKof) * 2;
            ldsm4(ah, aAddr);
            ldsm4(al, aAddr + (OFF_ALO - OFF_AHI));
            #pragma unroll
            for (int p = 0; p < 2; p++) {
                uint32_t bAddr = sbase + OFF_AHI + (uint32_t)((C0 + p * 16 + bRowOf) * STR_BF + ka + bKof) * 2;
                uint32_t bhv[4], blv[4];
                ldsm4(bhv, bAddr);
                ldsm4(blv, bAddr + (OFF_ALO - OFF_AHI));
                mma_bf16(acc[2 * p],     ah, bhv[0], bhv[1]);
                mma_bf16(acc[2 * p],     ah, blv[0], blv[1]);
                mma_bf16(acc[2 * p],     al, bhv[0], bhv[1]);
                mma_bf16(acc[2 * p + 1], ah, bhv[2], bhv[3]);
                mma_bf16(acc[2 * p + 1], ah, blv[2], blv[3]);
                mma_bf16(acc[2 * p + 1], al, bhv[2], bhv[3]);
            }
        }
        #pragma unroll
        for (int nt = 0; nt < 4; nt++) {
            int col = C0 + nt * 8 + qc;
            float i0v = sInv[col] * scale, i1v = sInv[col + 1] * scale;
            int r0 = R0 + qr;
            *(float2*)(sD + r0 * STR_D + col)       = make_float2(acc[nt][0] * i0v, acc[nt][1] * i1v);
            *(float2*)(sD + (r0 + 8) * STR_D + col) = make_float2(acc[nt][2] * i0v, acc[nt][3] * i1v);
        }
    }

    // ---- GEMM2: rel (hi only) -> bf16 sRel (unshifted), overlaying dead A arrays ----
    {
        float rac[4][4];
        #pragma unroll
        for (int nt = 0; nt < 4; nt++)
            #pragma unroll
            for (int u = 0; u < 4; u++) rac[nt][u] = 0.f;

        #pragma unroll
        for (int kt = 0; kt < 4; kt++) {
            int ka = kt * 16;
            uint32_t ah[4];
            uint32_t aAddr = sbase + OFF_AHI + (uint32_t)((R0 + aRowL) * STR_BF + ka + aKof) * 2;
            ldsm4(ah, aAddr);
            #pragma unroll
            for (int p = 0; p < 2; p++) {
                uint32_t bAddr = sbase + OFF_R + (uint32_t)((C0 + p * 16 + bRowOf) * STR_BF + ka + bKof) * 2;
                uint32_t brv[4];
                ldsm4(brv, bAddr);
                mma_bf16(rac[2 * p],     ah, brv[0], brv[1]);
                mma_bf16(rac[2 * p + 1], ah, brv[2], brv[3]);
            }
        }
        __syncthreads();   // all A reads done block-wide; safe to overlay
        #pragma unroll
        for (int nt = 0; nt < 4; nt++) {
            int jj = C0 + nt * 8 + qc;
            int i0 = R0 + qr;
            *(uint32_t*)(sm + OFF_RELS + (uint32_t)(i0 * 136 + jj) * 2) =
                packbf(__float2bfloat16_rn(rac[nt][0] * scale), __float2bfloat16_rn(rac[nt][1] * scale));
            *(uint32_t*)(sm + OFF_RELS + (uint32_t)((i0 + 8) * 136 + jj) * 2) =
                packbf(__float2bfloat16_rn(rac[nt][2] * scale), __float2bfloat16_rn(rac[nt][3] * scale));
        }
    }
    __syncthreads();

    // ---- in-register softmax (8 threads/row): dots + shifted rel + diag ----
    {
        int r = tid >> 3, q8 = tid & 7;
        const float4* rp = (const float4*)(sD + r * STR_D + q8 * 16);
        int jbase = q8 * 16;
        float v[16];
        #pragma unroll
        for (int j4 = 0; j4 < 4; j4++) {
            float4 x = rp[j4];
            v[4 * j4 + 0] = x.x; v[4 * j4 + 1] = x.y;
            v[4 * j4 + 2] = x.z; v[4 * j4 + 3] = x.w;
        }
        #pragma unroll
        for (int j = 0; j < 16; j++) {
            int src = 127 + jbase + j - r;
            if (src <= 127)
                v[j] += __bfloat162float(*(const __nv_bfloat16*)(sm + OFF_RELS + (uint32_t)(r * 136 + src) * 2));
        }
        int dcol = r - jbase;
        if (dcol >= 0 && dcol < 16) v[dcol] = -50000.0f;
        float mx = -1e30f;
        #pragma unroll
        for (int j = 0; j < 16; j++) mx = fmaxf(mx, v[j]);
        mx = fmaxf(mx, __shfl_xor_sync(0xFFFFFFFFu, mx, 1));
        mx = fmaxf(mx, __shfl_xor_sync(0xFFFFFFFFu, mx, 2));
        mx = fmaxf(mx, __shfl_xor_sync(0xFFFFFFFFu, mx, 4));
        float s = 0.f;
        #pragma unroll
        for (int j = 0; j < 16; j++) { v[j] = expf(v[j] - mx); s += v[j]; }
        s += __shfl_xor_sync(0xFFFFFFFFu, s, 1);
        s += __shfl_xor_sync(0xFFFFFFFFu, s, 2);
        s += __shfl_xor_sync(0xFFFFFFFFu, s, 4);
        float is = 1.f / s;
        __syncthreads();   // all fp32 reads done before bf16 overwrite of sD
        char* rowb = sm + OFF_D + (uint32_t)r * 528u;
        #pragma unroll
        for (int t = 0; t < 8; t++) {
            uint32_t hi, lo;
            split2(v[2 * t] * is, v[2 * t + 1] * is, hi, lo);
            *(uint32_t*)(rowb + q8 * 32 + 4 * t)       = hi;
            *(uint32_t*)(rowb + 256 + q8 * 32 + 4 * t) = lo;
        }
    }
    __syncthreads();

    // ---- GEMM3: AV; warp = 16 rows x 16 d-cols; A = P hi/lo from sD, B = V ldsm.trans ----
    {
        const int R0g = (warp & 7) << 4;
        const int n0 = (warp >> 3) << 4;
        float av[2][4];
        #pragma unroll
        for (int nt = 0; nt < 2; nt++)
            #pragma unroll
            for (int u = 0; u < 4; u++) av[nt][u] = 0.f;

        const int tKrow = ((lane >> 3) & 1) * 8 + (lane & 7);
        const int tDcol = ((lane >> 4) & 1) * 8;

        #pragma unroll
        for (int kt = 0; kt < 8; kt++) {
            int ka = kt * 16;
            uint32_t pAddr = sbase + OFF_D + (uint32_t)(R0g + aRowL) * 528u + (uint32_t)(ka + aKof) * 2;
            uint32_t ph[4], pl[4];
            ldsm4(ph, pAddr);
            ldsm4(pl, pAddr + 256);
            uint32_t vAddr = sbase + OFF_VHI + (uint32_t)((ka + tKrow) * STR_BF + n0 + tDcol) * 2;
            uint32_t vh[4], vl[4];
            ldsm4t(vh, vAddr);
            ldsm4t(vl, vAddr + (OFF_VLO - OFF_VHI));
            mma_bf16(av[0], ph, vh[0], vh[1]);
            mma_bf16(av[0], ph, vl[0], vl[1]);
            mma_bf16(av[0], pl, vh[0], vh[1]);
            mma_bf16(av[1], ph, vh[2], vh[3]);
            mma_bf16(av[1], ph, vl[2], vl[3]);
            mma_bf16(av[1], pl, vh[2], vh[3]);
        }
        int tok0 = sIdx[R0g + qr];
        int tok1 = sIdx[R0g + qr + 8];
        float* op0 = outNum + ((size_t)bh * T_ + tok0) * D_;
        float* op1 = outNum + ((size_t)bh * T_ + tok1) * D_;
        #pragma unroll
        for (int nt = 0; nt < 2; nt++) {
            int col = n0 + nt * 8 + qc;
            atomicAdd((float2*)(op0 + col), make_float2(av[nt][0], av[nt][1]));
            atomicAdd((float2*)(op1 + col), make_float2(av[nt][2], av[nt][3]));
        }
    }
    if (tid < 128) atomicAdd(&g_den[(size_t)bh * T_ + sIdx[tid]], 1.0f);
}

// ---------------- normalize out = num/(den+eps); write loss ----------------
__global__ void k_norm(float* __restrict__ out, int has_loss) {
    size_t gid = (size_t)blockIdx.x * 256 + threadIdx.x;
    float den = g_den[gid >> 4];
    float s = 1.f / (den + 1e-5f);
    float4* o4 = (float4*)out;
    float4 v = o4[gid];
    v.x *= s; v.y *= s; v.z *= s; v.w *= s;
    o4[gid] = v;
    if (gid == 0 && has_loss)
        out[(size_t)BH_ * T_ * D_] = g_loss * (0.0001f / (float)((size_t)BH_ * T_ * D_));
}

// ---------------- launch ----------------
extern "C" void kernel_launch(void* const* d_in, const int* in_sizes, int n_in,
                              void* d_out, int out_size) {
    const float* qk    = (const float*)d_in[0];
    const float* v     = (const float*)d_in[1];
    const float* means = (const float*)d_in[2];
    const float* relw  = (const float*)d_in[3];
    if (n_in >= 4 && in_sizes[2] == W_ * H_ * D_ && in_sizes[3] == H_ * C_ * D_) {
        relw  = (const float*)d_in[2];
        means = (const float*)d_in[3];
    }
    float* out = (float*)d_out;

    cudaMemsetAsync(d_out, 0, (size_t)out_size * sizeof(float), 0);
    k_zero<<<(BH_ * T_ + 255) / 256, 256>>>();

    dim3 g1(T_ / 64, BH_);
    k_dists<<<g1, 256>>>(qk, means);

    k_topk<<<BH_ * C_, 512>>>();

    cudaFuncSetAttribute(k_attn, cudaFuncAttributeMaxDynamicSharedMemorySize, SMEM_ATTN_BYTES);
    k_attn<<<BH_ * C_, NT_ATTN, SMEM_ATTN_BYTES>>>(qk, v, relw, out);

    int nf4 = BH_ * T_ * D_ / 4;
    k_norm<<<nf4 / 256, 256>>>(out, out_size > BH_ * T_ * D_ ? 1 : 0);
}

// round 13
// speedup vs baseline: 1.0115x; 1.0115x over previous
#include <cuda_runtime.h>
#include <cuda_bf16.h>
#include <cstdint>
#include <math.h>

#define B_ 4
#define H_ 8
#define T_ 8192
#define D_ 64
#define C_ 64
#define W_ 128
#define BH_ (B_*H_)

// ---------------- scratch ----------------
__device__ float g_dists[(size_t)BH_ * C_ * T_];   // [bh][c][t]
__device__ int   g_idx[BH_ * C_ * W_];
__device__ float g_den[BH_ * T_];
__device__ float g_loss;

__device__ __forceinline__ uint32_t packbf(__nv_bfloat16 a, __nv_bfloat16 b) {
    return ((uint32_t)__bfloat16_as_ushort(b) << 16) | (uint32_t)__bfloat16_as_ushort(a);
}
__device__ __forceinline__ void split2(float x, float y, uint32_t& hi, uint32_t& lo) {
    __nv_bfloat16 hx = __float2bfloat16_rn(x), hy = __float2bfloat16_rn(y);
    hi = packbf(hx, hy);
    lo = packbf(__float2bfloat16_rn(x - __bfloat162float(hx)),
                __float2bfloat16_rn(y - __bfloat162float(hy)));
}
__device__ __forceinline__ void mma_bf16(float (&c)[4], const uint32_t (&a)[4],
                                         uint32_t b0, uint32_t b1) {
    asm volatile("mma.sync.aligned.m16n8k16.row.col.f32.bf16.bf16.f32 "
        "{%0,%1,%2,%3}, {%4,%5,%6,%7}, {%8,%9}, {%0,%1,%2,%3};"
        : "+f"(c[0]), "+f"(c[1]), "+f"(c[2]), "+f"(c[3])
        : "r"(a[0]), "r"(a[1]), "r"(a[2]), "r"(a[3]), "r"(b0), "r"(b1));
}
__device__ __forceinline__ void ldsm4(uint32_t (&r)[4], uint32_t addr) {
    asm volatile("ldmatrix.sync.aligned.m8n8.x4.shared.b16 {%0,%1,%2,%3}, [%4];"
        : "=r"(r[0]), "=r"(r[1]), "=r"(r[2]), "=r"(r[3]) : "r"(addr));
}
__device__ __forceinline__ void ldsm4t(uint32_t (&r)[4], uint32_t addr) {
    asm volatile("ldmatrix.sync.aligned.m8n8.x4.trans.shared.b16 {%0,%1,%2,%3}, [%4];"
        : "=r"(r[0]), "=r"(r[1]), "=r"(r[2]), "=r"(r[3]) : "r"(addr));
}
__device__ __forceinline__ uint32_t smem_u32(const void* p) {
    uint32_t a;
    asm("{ .reg .u64 t; cvta.to.shared.u64 t, %1; cvt.u32.u64 %0, t; }" : "=r"(a) : "l"(p));
    return a;
}

// ---------------- zero den/loss ----------------
__global__ void k_zero() {
    int i = blockIdx.x * blockDim.x + threadIdx.x;
    if (i < BH_ * T_) g_den[i] = 0.f;
    if (i == 0) g_loss = 0.f;
}

// ---------------- dists = l2norm(qk) . means, fused commitment loss ----------------
__global__ void __launch_bounds__(256) k_dists(const float* __restrict__ qk,
                                               const float* __restrict__ means) {
    __shared__ float sQ[64 * 65];
    __shared__ float sM[64 * 65];
    __shared__ float sInv[64];
    int bh = blockIdx.y;
    int h = bh & (H_ - 1);
    int t0 = blockIdx.x * 64;
    const float* qp = qk + ((size_t)bh * T_ + t0) * D_;
    const float* mp = means + (size_t)h * C_ * D_;
    int tid = threadIdx.x;

    for (int i = tid; i < 64 * 16; i += 256) {
        int r = i >> 4, c4 = (i & 15) << 2;
        float4 a = *(const float4*)(qp + r * D_ + c4);
        sQ[r * 65 + c4 + 0] = a.x; sQ[r * 65 + c4 + 1] = a.y;
        sQ[r * 65 + c4 + 2] = a.z; sQ[r * 65 + c4 + 3] = a.w;
        float4 m = *(const float4*)(mp + r * D_ + c4);
        sM[r * 65 + c4 + 0] = m.x; sM[r * 65 + c4 + 1] = m.y;
        sM[r * 65 + c4 + 2] = m.z; sM[r * 65 + c4 + 3] = m.w;
    }
    __syncthreads();
    if (tid < 64) {
        float s = 0.f;
        #pragma unroll
        for (int k = 0; k < 64; k++) { float x = sQ[tid * 65 + k]; s += x * x; }
        sInv[tid] = 1.f / fmaxf(sqrtf(s), 1e-12f);
    }
    __syncthreads();

    int ty = tid >> 4, tx = tid & 15;
    float acc[4][4];
    #pragma unroll
    for (int u = 0; u < 4; u++)
        #pragma unroll
        for (int w = 0; w < 4; w++) acc[u][w] = 0.f;

    for (int k = 0; k < 64; k++) {
        float a[4], b[4];
        #pragma unroll
        for (int u = 0; u < 4; u++) a[u] = sQ[(ty * 4 + u) * 65 + k];
        #pragma unroll
        for (int w = 0; w < 4; w++) b[w] = sM[(tx * 4 + w) * 65 + k];
        #pragma unroll
        for (int u = 0; u < 4; u++)
            #pragma unroll
            for (int w = 0; w < 4; w++) acc[u][w] += a[u] * b[w];
    }
    __syncthreads();
    #pragma unroll
    for (int u = 0; u < 4; u++)
        #pragma unroll
        for (int w = 0; w < 4; w++)
            sQ[(tx * 4 + w) * 65 + (ty * 4 + u)] = acc[u][w] * sInv[ty * 4 + u];
    __syncthreads();
    float* dst = &g_dists[((size_t)bh * C_) * T_ + t0];
    for (int i = tid; i < 4096; i += 256) {
        int c = i >> 6, r = i & 63;
        dst[(size_t)c * T_ + r] = sQ[c * 65 + r];
    }
    if (tid < 64) {
        float m = -1e30f;
        #pragma unroll 8
        for (int c = 0; c < 64; c++) m = fmaxf(m, sQ[c * 65 + tid]);
        float v = 2.f - 2.f * m;
        #pragma unroll
        for (int off = 16; off > 0; off >>= 1) v += __shfl_down_sync(0xFFFFFFFFu, v, off);
        if ((tid & 31) == 0) atomicAdd(&g_loss, v);
    }
}

// ---------------- exact top-128: two-pass 2048-bin radix + rank-by-count tail ----------------
__device__ __forceinline__ unsigned kmap(float f) {
    unsigned u = __float_as_uint(f);
    return (u & 0x80000000u) ? ~u : (u | 0x80000000u);
}
__global__ void __launch_bounds__(512, 2) k_topk() {
    int row = blockIdx.x;
    const float* dp = g_dists + (size_t)row * T_;
    int tid = threadIdx.x;
    __shared__ int hist[2048];
    __shared__ int wsum[16];
    __shared__ int sSel, sNgt, sCntG, sCntC;
    __shared__ int sIdx[128];
    __shared__ unsigned long long cand[256];

    #pragma unroll
    for (int j = 0; j < 4; j++) hist[tid + j * 512] = 0;
    if (tid == 0) { sCntG = 0; sCntC = 0; }
    __syncthreads();

    // pass 1: stream + histogram
    #pragma unroll
    for (int k = 0; k < 16; k++) {
        unsigned key = kmap(dp[tid + (k << 9)]);
        atomicAdd(&hist[key >> 21], 1);
    }
    __syncthreads();

    // suffix counts
    int h0 = hist[4 * tid], h1 = hist[4 * tid + 1], h2 = hist[4 * tid + 2], h3 = hist[4 * tid + 3];
    int s = h0 + h1 + h2 + h3;
    int lane = tid & 31, wid = tid >> 5;
    int suf = s;
    #pragma unroll
    for (int off = 1; off < 32; off <<= 1) {
        int t = __shfl_down_sync(0xFFFFFFFFu, suf, off);
        if (lane + off < 32) suf += t;
    }
    if (lane == 0) wsum[wid] = suf;
    __syncthreads();
    if (tid < 16) {
        int v = wsum[tid];
        int sw = v;
        #pragma unroll
        for (int off = 1; off < 16; off <<= 1) {
            int t = __shfl_down_sync(0xFFFFu, sw, off);
            if (tid + off < 16) sw += t;
        }
        wsum[tid] = sw - v;
    }
    __syncthreads();
    int tailT = wsum[wid] + (suf - s);
    int suf3 = tailT + h3;
    int suf2 = suf3 + h2;
    int suf1 = suf2 + h1;
    int suf0 = suf1 + h0;
    if (suf0 >= 128 && suf1 < 128) { sSel = 4 * tid;     sNgt = suf1; }
    if (suf1 >= 128 && suf2 < 128) { sSel = 4 * tid + 1; sNgt = suf2; }
    if (suf2 >= 128 && suf3 < 128) { sSel = 4 * tid + 2; sNgt = suf3; }
    if (suf3 >= 128 && tailT < 128){ sSel = 4 * tid + 3; sNgt = tailT; }
    __syncthreads();
    unsigned selBin = (unsigned)sSel;
    int ngt = sNgt;

    // pass 2: re-read (L2-resident), classify
    #pragma unroll
    for (int k = 0; k < 16; k++) {
        unsigned key = kmap(dp[tid + (k << 9)]);
        unsigned b = key >> 21;
        if (b > selBin) {
            int p = atomicAdd(&sCntG, 1);
            sIdx[p] = tid + (k << 9);
        } else if (b == selBin) {
            int p = atomicAdd(&sCntC, 1);
            if (p < 256)
                cand[p] = ((unsigned long long)(~key) << 32) | (unsigned)(tid + (k << 9));
        }
    }
    __syncthreads();
    int cn = sCntC < 256 ? sCntC : 256;
    int need = 128 - ngt;
    // boundary: rank-by-count (key = ~value|index => smaller = better)
    for (int i = tid; i < cn; i += 512) {
        unsigned long long me = cand[i];
        int rank = 0;
        for (int j = 0; j < cn; j++) rank += (cand[j] < me);
        if (rank < need) sIdx[ngt + rank] = (int)(me & 0xFFFFFFFFu);
    }
    __syncthreads();
    // final ascending order by rank over 128 distinct indices (broadcast reads)
    if (tid < 128) {
        int myIdx = sIdx[tid];
        int rank = 0;
        #pragma unroll 8
        for (int j = 0; j < 128; j++) rank += (sIdx[j] < myIdx);
        g_idx[row * W_ + rank] = myIdx;
    }
}

// ---------------- fused gather + HMMA attention + scatter (1024 threads) ----------------
#define OFF_AHI   0u
#define OFF_ALO   18432u
#define OFF_R     36864u
#define OFF_VHI   55296u
#define OFF_VLO   73728u
#define OFF_D     92160u
#define OFF_INV   159744u
#define OFF_IDXS  160256u
#define SMEM_ATTN_BYTES 160768u

#define STR_BF 72
#define STR_D  132
#define NT_ATTN 1024

__global__ void __launch_bounds__(NT_ATTN)
k_attn(const float* __restrict__ qk,
       const float* __restrict__ vv,
       const float* __restrict__ relw,
       float* __restrict__ outNum) {
    extern __shared__ char sm[];
    float* sD   = (float*)(sm + OFF_D);
    float* sInv = (float*)(sm + OFF_INV);
    int*   sIdx = (int*)(sm + OFF_IDXS);
    uint32_t sbase = smem_u32(sm);

    int bhc = blockIdx.x;
    int bh = bhc >> 6;
    int h = bh & (H_ - 1);
    int tid = threadIdx.x;

    if (tid < 128) sIdx[tid] = g_idx[bhc * W_ + tid];
    __syncthreads();

    // ---- fused gather: q->A hi/lo + norms; v->V hi/lo; rel->R ----
    for (int i = tid; i < 128 * 16; i += NT_ATTN) {
        int r = i >> 4, c4 = (i & 15) << 2;
        int tok = sIdx[r];
        uint32_t off = (uint32_t)(r * STR_BF + c4) * 2;
        uint32_t hi0, lo0, hi1, lo1;

        float4 q4 = *(const float4*)(qk + ((size_t)bh * T_ + tok) * D_ + c4);
        split2(q4.x, q4.y, hi0, lo0);
        split2(q4.z, q4.w, hi1, lo1);
        *(uint32_t*)(sm + OFF_AHI + off)     = hi0;
        *(uint32_t*)(sm + OFF_AHI + off + 4) = hi1;
        *(uint32_t*)(sm + OFF_ALO + off)     = lo0;
        *(uint32_t*)(sm + OFF_ALO + off + 4) = lo1;
        float s = q4.x * q4.x + q4.y * q4.y + q4.z * q4.z + q4.w * q4.w;
        s += __shfl_xor_sync(0xFFFFFFFFu, s, 1);
        s += __shfl_xor_sync(0xFFFFFFFFu, s, 2);
        s += __shfl_xor_sync(0xFFFFFFFFu, s, 4);
        s += __shfl_xor_sync(0xFFFFFFFFu, s, 8);
        if ((tid & 15) == 0) sInv[r] = 1.f / fmaxf(sqrtf(s), 1e-12f);

        float4 v4 = *(const float4*)(vv + ((size_t)bh * T_ + tok) * D_ + c4);
        split2(v4.x, v4.y, hi0, lo0);
        split2(v4.z, v4.w, hi1, lo1);
        *(uint32_t*)(sm + OFF_VHI + off)     = hi0;
        *(uint32_t*)(sm + OFF_VHI + off + 4) = hi1;
        *(uint32_t*)(sm + OFF_VLO + off)     = lo0;
        *(uint32_t*)(sm + OFF_VLO + off + 4) = lo1;

        float4 r4 = *(const float4*)(relw + ((size_t)r * H_ + h) * D_ + c4);
        *(uint32_t*)(sm + OFF_R + off)     = packbf(__float2bfloat16_rn(r4.x), __float2bfloat16_rn(r4.y));
        *(uint32_t*)(sm + OFF_R + off + 4) = packbf(__float2bfloat16_rn(r4.z), __float2bfloat16_rn(r4.w));
    }
    __syncthreads();

    const int lane = tid & 31, warp = tid >> 5;
    const int qr = lane >> 2, qc = (lane & 3) << 1;
    const float scale = 0.125f;

    const int aKof = (lane >> 4) << 3;
    const int aRowL = lane & 15;
    const int bRowOf = ((lane >> 4) << 3) + (lane & 7);
    const int bKof = ((lane >> 3) & 1) << 3;

    const int R0 = (warp & 7) << 4;      // 8 row blocks of 16
    const int C0 = (warp >> 3) << 5;     // 4 col blocks of 32

    // ---- GEMM1: dots (3-term split), warp = 16 rows x 32 cols ----
    {
        float acc[4][4];
        #pragma unroll
        for (int nt = 0; nt < 4; nt++)
            #pragma unroll
            for (int u = 0; u < 4; u++) acc[nt][u] = 0.f;

        #pragma unroll
        for (int kt = 0; kt < 4; kt++) {
            int ka = kt * 16;
            uint32_t ah[4], al[4];
            uint32_t aAddr = sbase + OFF_AHI + (uint32_t)((R0 + aRowL) * STR_BF + ka + aKof) * 2;
            ldsm4(ah, aAddr);
            ldsm4(al, aAddr + (OFF_ALO - OFF_AHI));
            #pragma unroll
            for (int p = 0; p < 2; p++) {
                uint32_t bAddr = sbase + OFF_AHI + (uint32_t)((C0 + p * 16 + bRowOf) * STR_BF + ka + bKof) * 2;
                uint32_t bhv[4], blv[4];
                ldsm4(bhv, bAddr);
                ldsm4(blv, bAddr + (OFF_ALO - OFF_AHI));
                mma_bf16(acc[2 * p],     ah, bhv[0], bhv[1]);
                mma_bf16(acc[2 * p],     ah, blv[0], blv[1]);
                mma_bf16(acc[2 * p],     al, bhv[0], bhv[1]);
                mma_bf16(acc[2 * p + 1], ah, bhv[2], bhv[3]);
                mma_bf16(acc[2 * p + 1], ah, blv[2], blv[3]);
                mma_bf16(acc[2 * p + 1], al, bhv[2], bhv[3]);
            }
        }
        #pragma unroll
        for (int nt = 0; nt < 4; nt++) {
            int col = C0 + nt * 8 + qc;
            float i0v = sInv[col] * scale, i1v = sInv[col + 1] * scale;
            int r0 = R0 + qr;
            sD[r0 * STR_D + col]           = acc[nt][0] * i0v;
            sD[r0 * STR_D + col + 1]       = acc[nt][1] * i1v;
            sD[(r0 + 8) * STR_D + col]     = acc[nt][2] * i0v;
            sD[(r0 + 8) * STR_D + col + 1] = acc[nt][3] * i1v;
        }
    }
    __syncthreads();

    // ---- GEMM2: rel (hi only), shifted add into sD ----
    {
        float rac[4][4];
        #pragma unroll
        for (int nt = 0; nt < 4; nt++)
            #pragma unroll
            for (int u = 0; u < 4; u++) rac[nt][u] = 0.f;

        #pragma unroll
        for (int kt = 0; kt < 4; kt++) {
            int ka = kt * 16;
            uint32_t ah[4];
            uint32_t aAddr = sbase + OFF_AHI + (uint32_t)((R0 + aRowL) * STR_BF + ka + aKof) * 2;
            ldsm4(ah, aAddr);
            #pragma unroll
            for (int p = 0; p < 2; p++) {
                uint32_t bAddr = sbase + OFF_R + (uint32_t)((C0 + p * 16 + bRowOf) * STR_BF + ka + bKof) * 2;
                uint32_t brv[4];
                ldsm4(brv, bAddr);
                mma_bf16(rac[2 * p],     ah, brv[0], brv[1]);
                mma_bf16(rac[2 * p + 1], ah, brv[2], brv[3]);
            }
        }
        #pragma unroll
        for (int nt = 0; nt < 4; nt++) {
            int jj = C0 + nt * 8 + qc;
            int i0 = R0 + qr;
            int j0 = i0 + jj - 127;
            if (j0 >= 0)                     sD[i0 * STR_D + j0]     += rac[nt][0] * scale;
            if (j0 + 1 >= 0 && j0 + 1 <= i0) sD[i0 * STR_D + j0 + 1] += rac[nt][1] * scale;
            int i1 = i0 + 8;
            int j1 = i1 + jj - 127;
            if (j1 >= 0)                     sD[i1 * STR_D + j1]     += rac[nt][2] * scale;
            if (j1 + 1 >= 0 && j1 + 1 <= i1) sD[i1 * STR_D + j1 + 1] += rac[nt][3] * scale;
        }
    }
    __syncthreads();

    // ---- in-register softmax (8 threads/row) + P bf16 hi/lo into sD rows ----
    {
        int r = tid >> 3, q8 = tid & 7;
        const float4* rp = (const float4*)(sD + r * STR_D + q8 * 16);
        int dcol = r - q8 * 16;
        float v[16];
        #pragma unroll
        for (int j4 = 0; j4 < 4; j4++) {
            float4 x = rp[j4];
            v[4 * j4 + 0] = (4 * j4 + 0 == dcol) ? -50000.0f : x.x;
            v[4 * j4 + 1] = (4 * j4 + 1 == dcol) ? -50000.0f : x.y;
            v[4 * j4 + 2] = (4 * j4 + 2 == dcol) ? -50000.0f : x.z;
            v[4 * j4 + 3] = (4 * j4 + 3 == dcol) ? -50000.0f : x.w;
        }
        float mx = -1e30f;
        #pragma unroll
        for (int j = 0; j < 16; j++) mx = fmaxf(mx, v[j]);
        mx = fmaxf(mx, __shfl_xor_sync(0xFFFFFFFFu, mx, 1));
        mx = fmaxf(mx, __shfl_xor_sync(0xFFFFFFFFu, mx, 2));
        mx = fmaxf(mx, __shfl_xor_sync(0xFFFFFFFFu, mx, 4));
        float s = 0.f;
        #pragma unroll
        for (int j = 0; j < 16; j++) { v[j] = expf(v[j] - mx); s += v[j]; }
        s += __shfl_xor_sync(0xFFFFFFFFu, s, 1);
        s += __shfl_xor_sync(0xFFFFFFFFu, s, 2);
        s += __shfl_xor_sync(0xFFFFFFFFu, s, 4);
        float is = 1.f / s;
        __syncthreads();   // all fp32 reads done before bf16 overwrite
        char* rowb = sm + OFF_D + (uint32_t)r * 528u;
        #pragma unroll
        for (int t = 0; t < 8; t++) {
            uint32_t hi, lo;
            split2(v[2 * t] * is, v[2 * t + 1] * is, hi, lo);
            *(uint32_t*)(rowb + q8 * 32 + 4 * t)       = hi;
            *(uint32_t*)(rowb + 256 + q8 * 32 + 4 * t) = lo;
        }
    }
    __syncthreads();

    // ---- GEMM3: AV; warp = 16 rows x 16 d-cols; A = P hi/lo from sD, B = V ldsm.trans ----
    {
        const int R0g = (warp & 7) << 4;
        const int n0 = (warp >> 3) << 4;
        float av[2][4];
        #pragma unroll
        for (int nt = 0; nt < 2; nt++)
            #pragma unroll
            for (int u = 0; u < 4; u++) av[nt][u] = 0.f;

        const int tKrow = ((lane >> 3) & 1) * 8 + (lane & 7);
        const int tDcol = ((lane >> 4) & 1) * 8;

        #pragma unroll
        for (int kt = 0; kt < 8; kt++) {
            int ka = kt * 16;
            uint32_t pAddr = sbase + OFF_D + (uint32_t)(R0g + aRowL) * 528u + (uint32_t)(ka + aKof) * 2;
            uint32_t ph[4], pl[4];
            ldsm4(ph, pAddr);
            ldsm4(pl, pAddr + 256);
            uint32_t vAddr = sbase + OFF_VHI + (uint32_t)((ka + tKrow) * STR_BF + n0 + tDcol) * 2;
            uint32_t vh[4], vl[4];
            ldsm4t(vh, vAddr);
            ldsm4t(vl, vAddr + (OFF_VLO - OFF_VHI));
            mma_bf16(av[0], ph, vh[0], vh[1]);
            mma_bf16(av[0], ph, vl[0], vl[1]);
            mma_bf16(av[0], pl, vh[0], vh[1]);
            mma_bf16(av[1], ph, vh[2], vh[3]);
            mma_bf16(av[1], ph, vl[2], vl[3]);
            mma_bf16(av[1], pl, vh[2], vh[3]);
        }
        int tok0 = sIdx[R0g + qr];
        int tok1 = sIdx[R0g + qr + 8];
        float* op0 = outNum + ((size_t)bh * T_ + tok0) * D_;
        float* op1 = outNum + ((size_t)bh * T_ + tok1) * D_;
        #pragma unroll
        for (int nt = 0; nt < 2; nt++) {
            int col = n0 + nt * 8 + qc;
            atomicAdd((float2*)(op0 + col), make_float2(av[nt][0], av[nt][1]));
            atomicAdd((float2*)(op1 + col), make_float2(av[nt][2], av[nt][3]));
        }
    }
    if (tid < 128) atomicAdd(&g_den[(size_t)bh * T_ + sIdx[tid]], 1.0f);
}

// ---------------- normalize out = num/(den+eps); write loss ----------------
__global__ void k_norm(float* __restrict__ out, int has_loss) {
    size_t gid = (size_t)blockIdx.x * 256 + threadIdx.x;
    float den = g_den[gid >> 4];
    float s = 1.f / (den + 1e-5f);
    float4* o4 = (float4*)out;
    float4 v = o4[gid];
    v.x *= s; v.y *= s; v.z *= s; v.w *= s;
    o4[gid] = v;
    if (gid == 0 && has_loss)
        out[(size_t)BH_ * T_ * D_] = g_loss * (0.0001f / (float)((size_t)BH_ * T_ * D_));
}

// ---------------- launch ----------------
extern "C" void kernel_launch(void* const* d_in, const int* in_sizes, int n_in,
                              void* d_out, int out_size) {
    const float* qk    = (const float*)d_in[0];
    const float* v     = (const float*)d_in[1];
    const float* means = (const float*)d_in[2];
    const float* relw  = (const float*)d_in[3];
    if (n_in >= 4 && in_sizes[2] == W_ * H_ * D_ && in_sizes[3] == H_ * C_ * D_) {
        relw  = (const float*)d_in[2];
        means = (const float*)d_in[3];
    }
    float* out = (float*)d_out;

    cudaMemsetAsync(d_out, 0, (size_t)out_size * sizeof(float), 0);
    k_zero<<<(BH_ * T_ + 255) / 256, 256>>>();

    dim3 g1(T_ / 64, BH_);
    k_dists<<<g1, 256>>>(qk, means);

    k_topk<<<BH_ * C_, 512>>>();

    cudaFuncSetAttribute(k_attn, cudaFuncAttributeMaxDynamicSharedMemorySize, SMEM_ATTN_BYTES);
    k_attn<<<BH_ * C_, NT_ATTN, SMEM_ATTN_BYTES>>>(qk, v, relw, out);

    int nf4 = BH_ * T_ * D_ / 4;
    k_norm<<<nf4 / 256, 256>>>(out, out_size > BH_ * T_ * D_ ? 1 : 0);
}

// round 14
// speedup vs baseline: 1.0919x; 1.0794x over previous
#include <cuda_runtime.h>
#include <cuda_bf16.h>
#include <cuda_fp16.h>
#include <cstdint>
#include <math.h>

#define B_ 4
#define H_ 8
#define T_ 8192
#define D_ 64
#define C_ 64
#define W_ 128
#define BH_ (B_*H_)

// ---------------- scratch ----------------
__device__ float g_dists[(size_t)BH_ * C_ * T_];   // [bh][c][t]
__device__ int   g_idx[BH_ * C_ * W_];
__device__ float g_den[BH_ * T_];
__device__ float g_loss;

__device__ __forceinline__ uint32_t packh(__half a, __half b) {
    return ((uint32_t)__half_as_ushort(b) << 16) | (uint32_t)__half_as_ushort(a);
}
__device__ __forceinline__ uint32_t pack1h(float x, float y) {
    return packh(__float2half_rn(x), __float2half_rn(y));
}
__device__ __forceinline__ void splith2(float x, float y, uint32_t& hi, uint32_t& lo) {
    __half hx = __float2half_rn(x), hy = __float2half_rn(y);
    hi = packh(hx, hy);
    lo = packh(__float2half_rn(x - __half2float(hx)),
               __float2half_rn(y - __half2float(hy)));
}
__device__ __forceinline__ void mma_f16(float (&c)[4], const uint32_t (&a)[4],
                                        uint32_t b0, uint32_t b1) {
    asm volatile("mma.sync.aligned.m16n8k16.row.col.f32.f16.f16.f32 "
        "{%0,%1,%2,%3}, {%4,%5,%6,%7}, {%8,%9}, {%0,%1,%2,%3};"
        : "+f"(c[0]), "+f"(c[1]), "+f"(c[2]), "+f"(c[3])
        : "r"(a[0]), "r"(a[1]), "r"(a[2]), "r"(a[3]), "r"(b0), "r"(b1));
}
__device__ __forceinline__ void ldsm4(uint32_t (&r)[4], uint32_t addr) {
    asm volatile("ldmatrix.sync.aligned.m8n8.x4.shared.b16 {%0,%1,%2,%3}, [%4];"
        : "=r"(r[0]), "=r"(r[1]), "=r"(r[2]), "=r"(r[3]) : "r"(addr));
}
__device__ __forceinline__ void ldsm4t(uint32_t (&r)[4], uint32_t addr) {
    asm volatile("ldmatrix.sync.aligned.m8n8.x4.trans.shared.b16 {%0,%1,%2,%3}, [%4];"
        : "=r"(r[0]), "=r"(r[1]), "=r"(r[2]), "=r"(r[3]) : "r"(addr));
}
__device__ __forceinline__ uint32_t smem_u32(const void* p) {
    uint32_t a;
    asm("{ .reg .u64 t; cvta.to.shared.u64 t, %1; cvt.u32.u64 %0, t; }" : "=r"(a) : "l"(p));
    return a;
}

// ---------------- zero den/loss ----------------
__global__ void k_zero() {
    int i = blockIdx.x * blockDim.x + threadIdx.x;
    if (i < BH_ * T_) g_den[i] = 0.f;
    if (i == 0) g_loss = 0.f;
}

// ---------------- dists = l2norm(qk) . means, fused commitment loss ----------------
__global__ void __launch_bounds__(256) k_dists(const float* __restrict__ qk,
                                               const float* __restrict__ means) {
    __shared__ float sQ[64 * 65];
    __shared__ float sM[64 * 65];
    __shared__ float sInv[64];
    int bh = blockIdx.y;
    int h = bh & (H_ - 1);
    int t0 = blockIdx.x * 64;
    const float* qp = qk + ((size_t)bh * T_ + t0) * D_;
    const float* mp = means + (size_t)h * C_ * D_;
    int tid = threadIdx.x;

    for (int i = tid; i < 64 * 16; i += 256) {
        int r = i >> 4, c4 = (i & 15) << 2;
        float4 a = *(const float4*)(qp + r * D_ + c4);
        sQ[r * 65 + c4 + 0] = a.x; sQ[r * 65 + c4 + 1] = a.y;
        sQ[r * 65 + c4 + 2] = a.z; sQ[r * 65 + c4 + 3] = a.w;
        float4 m = *(const float4*)(mp + r * D_ + c4);
        sM[r * 65 + c4 + 0] = m.x; sM[r * 65 + c4 + 1] = m.y;
        sM[r * 65 + c4 + 2] = m.z; sM[r * 65 + c4 + 3] = m.w;
    }
    __syncthreads();
    if (tid < 64) {
        float s = 0.f;
        #pragma unroll
        for (int k = 0; k < 64; k++) { float x = sQ[tid * 65 + k]; s += x * x; }
        sInv[tid] = 1.f / fmaxf(sqrtf(s), 1e-12f);
    }
    __syncthreads();

    int ty = tid >> 4, tx = tid & 15;
    float acc[4][4];
    #pragma unroll
    for (int u = 0; u < 4; u++)
        #pragma unroll
        for (int w = 0; w < 4; w++) acc[u][w] = 0.f;

    for (int k = 0; k < 64; k++) {
        float a[4], b[4];
        #pragma unroll
        for (int u = 0; u < 4; u++) a[u] = sQ[(ty * 4 + u) * 65 + k];
        #pragma unroll
        for (int w = 0; w < 4; w++) b[w] = sM[(tx * 4 + w) * 65 + k];
        #pragma unroll
        for (int u = 0; u < 4; u++)
            #pragma unroll
            for (int w = 0; w < 4; w++) acc[u][w] += a[u] * b[w];
    }
    __syncthreads();
    #pragma unroll
    for (int u = 0; u < 4; u++)
        #pragma unroll
        for (int w = 0; w < 4; w++)
            sQ[(tx * 4 + w) * 65 + (ty * 4 + u)] = acc[u][w] * sInv[ty * 4 + u];
    __syncthreads();
    float* dst = &g_dists[((size_t)bh * C_) * T_ + t0];
    for (int i = tid; i < 4096; i += 256) {
        int c = i >> 6, r = i & 63;
        dst[(size_t)c * T_ + r] = sQ[c * 65 + r];
    }
    if (tid < 64) {
        float m = -1e30f;
        #pragma unroll 8
        for (int c = 0; c < 64; c++) m = fmaxf(m, sQ[c * 65 + tid]);
        float v = 2.f - 2.f * m;
        #pragma unroll
        for (int off = 16; off > 0; off >>= 1) v += __shfl_down_sync(0xFFFFFFFFu, v, off);
        if ((tid & 31) == 0) atomicAdd(&g_loss, v);
    }
}

// ---------------- exact top-128: two-pass 2048-bin radix + rank-by-count tail ----------------
__device__ __forceinline__ unsigned kmap(float f) {
    unsigned u = __float_as_uint(f);
    return (u & 0x80000000u) ? ~u : (u | 0x80000000u);
}
__global__ void __launch_bounds__(512, 2) k_topk() {
    int row = blockIdx.x;
    const float* dp = g_dists + (size_t)row * T_;
    int tid = threadIdx.x;
    __shared__ int hist[2048];
    __shared__ int wsum[16];
    __shared__ int sSel, sNgt, sCntG, sCntC;
    __shared__ int sIdx[128];
    __shared__ unsigned long long cand[256];

    #pragma unroll
    for (int j = 0; j < 4; j++) hist[tid + j * 512] = 0;
    if (tid == 0) { sCntG = 0; sCntC = 0; }
    __syncthreads();

    #pragma unroll
    for (int k = 0; k < 16; k++) {
        unsigned key = kmap(dp[tid + (k << 9)]);
        atomicAdd(&hist[key >> 21], 1);
    }
    __syncthreads();

    int h0 = hist[4 * tid], h1 = hist[4 * tid + 1], h2 = hist[4 * tid + 2], h3 = hist[4 * tid + 3];
    int s = h0 + h1 + h2 + h3;
    int lane = tid & 31, wid = tid >> 5;
    int suf = s;
    #pragma unroll
    for (int off = 1; off < 32; off <<= 1) {
        int t = __shfl_down_sync(0xFFFFFFFFu, suf, off);
        if (lane + off < 32) suf += t;
    }
    if (lane == 0) wsum[wid] = suf;
    __syncthreads();
    if (tid < 16) {
        int v = wsum[tid];
        int sw = v;
        #pragma unroll
        for (int off = 1; off < 16; off <<= 1) {
            int t = __shfl_down_sync(0xFFFFu, sw, off);
            if (tid + off < 16) sw += t;
        }
        wsum[tid] = sw - v;
    }
    __syncthreads();
    int tailT = wsum[wid] + (suf - s);
    int suf3 = tailT + h3;
    int suf2 = suf3 + h2;
    int suf1 = suf2 + h1;
    int suf0 = suf1 + h0;
    if (suf0 >= 128 && suf1 < 128) { sSel = 4 * tid;     sNgt = suf1; }
    if (suf1 >= 128 && suf2 < 128) { sSel = 4 * tid + 1; sNgt = suf2; }
    if (suf2 >= 128 && suf3 < 128) { sSel = 4 * tid + 2; sNgt = suf3; }
    if (suf3 >= 128 && tailT < 128){ sSel = 4 * tid + 3; sNgt = tailT; }
    __syncthreads();
    unsigned selBin = (unsigned)sSel;
    int ngt = sNgt;

    #pragma unroll
    for (int k = 0; k < 16; k++) {
        unsigned key = kmap(dp[tid + (k << 9)]);
        unsigned b = key >> 21;
        if (b > selBin) {
            int p = atomicAdd(&sCntG, 1);
            sIdx[p] = tid + (k << 9);
        } else if (b == selBin) {
            int p = atomicAdd(&sCntC, 1);
            if (p < 256)
                cand[p] = ((unsigned long long)(~key) << 32) | (unsigned)(tid + (k << 9));
        }
    }
    __syncthreads();
    int cn = sCntC < 256 ? sCntC : 256;
    int need = 128 - ngt;
    for (int i = tid; i < cn; i += 512) {
        unsigned long long me = cand[i];
        int rank = 0;
        for (int j = 0; j < cn; j++) rank += (cand[j] < me);
        if (rank < need) sIdx[ngt + rank] = (int)(me & 0xFFFFFFFFu);
    }
    __syncthreads();
    if (tid < 128) {
        int myIdx = sIdx[tid];
        int rank = 0;
        #pragma unroll 8
        for (int j = 0; j < 128; j++) rank += (sIdx[j] < myIdx);
        g_idx[row * W_ + rank] = myIdx;
    }
}

// ---------------- fused gather + HMMA(fp16) attention + scatter (1024 threads) ----------------
#define OFF_AHI   0u
#define OFF_ALO   18432u
#define OFF_R     36864u
#define OFF_VHI   55296u
#define OFF_D     92160u
#define OFF_INV   159744u
#define OFF_IDXS  160256u
#define SMEM_ATTN_BYTES 160768u

#define STR_BF 72
#define STR_D  132
#define NT_ATTN 1024

__global__ void __launch_bounds__(NT_ATTN)
k_attn(const float* __restrict__ qk,
       const float* __restrict__ vv,
       const float* __restrict__ relw,
       float* __restrict__ outNum) {
    extern __shared__ char sm[];
    float* sD   = (float*)(sm + OFF_D);
    float* sInv = (float*)(sm + OFF_INV);
    int*   sIdx = (int*)(sm + OFF_IDXS);
    uint32_t sbase = smem_u32(sm);

    int bhc = blockIdx.x;
    int bh = bhc >> 6;
    int h = bh & (H_ - 1);
    int tid = threadIdx.x;

    if (tid < 128) sIdx[tid] = g_idx[bhc * W_ + tid];
    __syncthreads();

    // ---- fused gather: q->A hi/lo (fp16) + norms; v->V fp16; rel->R fp16 ----
    for (int i = tid; i < 128 * 16; i += NT_ATTN) {
        int r = i >> 4, c4 = (i & 15) << 2;
        int tok = sIdx[r];
        uint32_t off = (uint32_t)(r * STR_BF + c4) * 2;
        uint32_t hi0, lo0, hi1, lo1;

        float4 q4 = *(const float4*)(qk + ((size_t)bh * T_ + tok) * D_ + c4);
        splith2(q4.x, q4.y, hi0, lo0);
        splith2(q4.z, q4.w, hi1, lo1);
        *(uint32_t*)(sm + OFF_AHI + off)     = hi0;
        *(uint32_t*)(sm + OFF_AHI + off + 4) = hi1;
        *(uint32_t*)(sm + OFF_ALO + off)     = lo0;
        *(uint32_t*)(sm + OFF_ALO + off + 4) = lo1;
        float s = q4.x * q4.x + q4.y * q4.y + q4.z * q4.z + q4.w * q4.w;
        s += __shfl_xor_sync(0xFFFFFFFFu, s, 1);
        s += __shfl_xor_sync(0xFFFFFFFFu, s, 2);
        s += __shfl_xor_sync(0xFFFFFFFFu, s, 4);
        s += __shfl_xor_sync(0xFFFFFFFFu, s, 8);
        if ((tid & 15) == 0) sInv[r] = 1.f / fmaxf(sqrtf(s), 1e-12f);

        float4 v4 = *(const float4*)(vv + ((size_t)bh * T_ + tok) * D_ + c4);
        *(uint32_t*)(sm + OFF_VHI + off)     = pack1h(v4.x, v4.y);
        *(uint32_t*)(sm + OFF_VHI + off + 4) = pack1h(v4.z, v4.w);

        float4 r4 = *(const float4*)(relw + ((size_t)r * H_ + h) * D_ + c4);
        *(uint32_t*)(sm + OFF_R + off)     = pack1h(r4.x, r4.y);
        *(uint32_t*)(sm + OFF_R + off + 4) = pack1h(r4.z, r4.w);
    }
    __syncthreads();

    const int lane = tid & 31, warp = tid >> 5;
    const int qr = lane >> 2, qc = (lane & 3) << 1;
    const float scale = 0.125f;

    const int aKof = (lane >> 4) << 3;
    const int aRowL = lane & 15;
    const int bRowOf = ((lane >> 4) << 3) + (lane & 7);
    const int bKof = ((lane >> 3) & 1) << 3;

    const int R0 = (warp & 7) << 4;      // 8 row blocks of 16
    const int C0 = (warp >> 3) << 5;     // 4 col blocks of 32

    // ---- GEMM1: dots (fp16 3-term split), warp = 16 rows x 32 cols ----
    {
        float acc[4][4];
        #pragma unroll
        for (int nt = 0; nt < 4; nt++)
            #pragma unroll
            for (int u = 0; u < 4; u++) acc[nt][u] = 0.f;

        #pragma unroll
        for (int kt = 0; kt < 4; kt++) {
            int ka = kt * 16;
            uint32_t ah[4], al[4];
            uint32_t aAddr = sbase + OFF_AHI + (uint32_t)((R0 + aRowL) * STR_BF + ka + aKof) * 2;
            ldsm4(ah, aAddr);
            ldsm4(al, aAddr + (OFF_ALO - OFF_AHI));
            #pragma unroll
            for (int p = 0; p < 2; p++) {
                uint32_t bAddr = sbase + OFF_AHI + (uint32_t)((C0 + p * 16 + bRowOf) * STR_BF + ka + bKof) * 2;
                uint32_t bhv[4], blv[4];
                ldsm4(bhv, bAddr);
                ldsm4(blv, bAddr + (OFF_ALO - OFF_AHI));
                mma_f16(acc[2 * p],     ah, bhv[0], bhv[1]);
                mma_f16(acc[2 * p],     ah, blv[0], blv[1]);
                mma_f16(acc[2 * p],     al, bhv[0], bhv[1]);
                mma_f16(acc[2 * p + 1], ah, bhv[2], bhv[3]);
                mma_f16(acc[2 * p + 1], ah, blv[2], blv[3]);
                mma_f16(acc[2 * p + 1], al, bhv[2], bhv[3]);
            }
        }
        #pragma unroll
        for (int nt = 0; nt < 4; nt++) {
            int col = C0 + nt * 8 + qc;
            float i0v = sInv[col] * scale, i1v = sInv[col + 1] * scale;
            int r0 = R0 + qr;
            sD[r0 * STR_D + col]           = acc[nt][0] * i0v;
            sD[r0 * STR_D + col + 1]       = acc[nt][1] * i1v;
            sD[(r0 + 8) * STR_D + col]     = acc[nt][2] * i0v;
            sD[(r0 + 8) * STR_D + col + 1] = acc[nt][3] * i1v;
        }
    }
    __syncthreads();

    // ---- GEMM2: rel (fp16, single term), shifted add into sD ----
    {
        float rac[4][4];
        #pragma unroll
        for (int nt = 0; nt < 4; nt++)
            #pragma unroll
            for (int u = 0; u < 4; u++) rac[nt][u] = 0.f;

        #pragma unroll
        for (int kt = 0; kt < 4; kt++) {
            int ka = kt * 16;
            uint32_t ah[4];
            uint32_t aAddr = sbase + OFF_AHI + (uint32_t)((R0 + aRowL) * STR_BF + ka + aKof) * 2;
            ldsm4(ah, aAddr);
            #pragma unroll
            for (int p = 0; p < 2; p++) {
                uint32_t bAddr = sbase + OFF_R + (uint32_t)((C0 + p * 16 + bRowOf) * STR_BF + ka + bKof) * 2;
                uint32_t brv[4];
                ldsm4(brv, bAddr);
                mma_f16(rac[2 * p],     ah, brv[0], brv[1]);
                mma_f16(rac[2 * p + 1], ah, brv[2], brv[3]);
            }
        }
        #pragma unroll
        for (int nt = 0; nt < 4; nt++) {
            int jj = C0 + nt * 8 + qc;
            int i0 = R0 + qr;
            int j0 = i0 + jj - 127;
            if (j0 >= 0)                     sD[i0 * STR_D + j0]     += rac[nt][0] * scale;
            if (j0 + 1 >= 0 && j0 + 1 <= i0) sD[i0 * STR_D + j0 + 1] += rac[nt][1] * scale;
            int i1 = i0 + 8;
            int j1 = i1 + jj - 127;
            if (j1 >= 0)                     sD[i1 * STR_D + j1]     += rac[nt][2] * scale;
            if (j1 + 1 >= 0 && j1 + 1 <= i1) sD[i1 * STR_D + j1 + 1] += rac[nt][3] * scale;
        }
    }
    __syncthreads();

    // ---- in-register softmax (8 threads/row) + P fp16 (single) into sD rows ----
    {
        int r = tid >> 3, q8 = tid & 7;
        const float4* rp = (const float4*)(sD + r * STR_D + q8 * 16);
        int dcol = r - q8 * 16;
        float v[16];
        #pragma unroll
        for (int j4 = 0; j4 < 4; j4++) {
            float4 x = rp[j4];
            v[4 * j4 + 0] = (4 * j4 + 0 == dcol) ? -50000.0f : x.x;
            v[4 * j4 + 1] = (4 * j4 + 1 == dcol) ? -50000.0f : x.y;
            v[4 * j4 + 2] = (4 * j4 + 2 == dcol) ? -50000.0f : x.z;
            v[4 * j4 + 3] = (4 * j4 + 3 == dcol) ? -50000.0f : x.w;
        }
        float mx = -1e30f;
        #pragma unroll
        for (int j = 0; j < 16; j++) mx = fmaxf(mx, v[j]);
        mx = fmaxf(mx, __shfl_xor_sync(0xFFFFFFFFu, mx, 1));
        mx = fmaxf(mx, __shfl_xor_sync(0xFFFFFFFFu, mx, 2));
        mx = fmaxf(mx, __shfl_xor_sync(0xFFFFFFFFu, mx, 4));
        float s = 0.f;
        #pragma unroll
        for (int j = 0; j < 16; j++) { v[j] = expf(v[j] - mx); s += v[j]; }
        s += __shfl_xor_sync(0xFFFFFFFFu, s, 1);
        s += __shfl_xor_sync(0xFFFFFFFFu, s, 2);
        s += __shfl_xor_sync(0xFFFFFFFFu, s, 4);
        float is = 1.f / s;
        __syncthreads();   // all fp32 reads done before fp16 overwrite
        char* rowb = sm + OFF_D + (uint32_t)r * 528u;
        #pragma unroll
        for (int t = 0; t < 8; t++)
            *(uint32_t*)(rowb + q8 * 32 + 4 * t) = pack1h(v[2 * t] * is, v[2 * t + 1] * is);
    }
    __syncthreads();

    // ---- GEMM3: AV single fp16 term; warp = 16 rows x 16 d-cols ----
    {
        const int R0g = (warp & 7) << 4;
        const int n0 = (warp >> 3) << 4;
        float av[2][4];
        #pragma unroll
        for (int nt = 0; nt < 2; nt++)
            #pragma unroll
            for (int u = 0; u < 4; u++) av[nt][u] = 0.f;

        const int tKrow = ((lane >> 3) & 1) * 8 + (lane & 7);
        const int tDcol = ((lane >> 4) & 1) * 8;

        #pragma unroll
        for (int kt = 0; kt < 8; kt++) {
            int ka = kt * 16;
            uint32_t pAddr = sbase + OFF_D + (uint32_t)(R0g + aRowL) * 528u + (uint32_t)(ka + aKof) * 2;
            uint32_t ph[4];
            ldsm4(ph, pAddr);
            uint32_t vAddr = sbase + OFF_VHI + (uint32_t)((ka + tKrow) * STR_BF + n0 + tDcol) * 2;
            uint32_t vh[4];
            ldsm4t(vh, vAddr);
            mma_f16(av[0], ph, vh[0], vh[1]);
            mma_f16(av[1], ph, vh[2], vh[3]);
        }
        int tok0 = sIdx[R0g + qr];
        int tok1 = sIdx[R0g + qr + 8];
        float* op0 = outNum + ((size_t)bh * T_ + tok0) * D_;
        float* op1 = outNum + ((size_t)bh * T_ + tok1) * D_;
        #pragma unroll
        for (int nt = 0; nt < 2; nt++) {
            int col = n0 + nt * 8 + qc;
            atomicAdd((float2*)(op0 + col), make_float2(av[nt][0], av[nt][1]));
            atomicAdd((float2*)(op1 + col), make_float2(av[nt][2], av[nt][3]));
        }
    }
    if (tid < 128) atomicAdd(&g_den[(size_t)bh * T_ + sIdx[tid]], 1.0f);
}

// ---------------- normalize out = num/(den+eps); write loss ----------------
__global__ void k_norm(float* __restrict__ out, int has_loss) {
    size_t gid = (size_t)blockIdx.x * 256 + threadIdx.x;
    float den = g_den[gid >> 4];
    float s = 1.f / (den + 1e-5f);
    float4* o4 = (float4*)out;
    float4 v = o4[gid];
    v.x *= s; v.y *= s; v.z *= s; v.w *= s;
    o4[gid] = v;
    if (gid == 0 && has_loss)
        out[(size_t)BH_ * T_ * D_] = g_loss * (0.0001f / (float)((size_t)BH_ * T_ * D_));
}

// ---------------- launch ----------------
extern "C" void kernel_launch(void* const* d_in, const int* in_sizes, int n_in,
                              void* d_out, int out_size) {
    const float* qk    = (const float*)d_in[0];
    const float* v     = (const float*)d_in[1];
    const float* means = (const float*)d_in[2];
    const float* relw  = (const float*)d_in[3];
    if (n_in >= 4 && in_sizes[2] == W_ * H_ * D_ && in_sizes[3] == H_ * C_ * D_) {
        relw  = (const float*)d_in[2];
        means = (const float*)d_in[3];
    }
    float* out = (float*)d_out;

    cudaMemsetAsync(d_out, 0, (size_t)out_size * sizeof(float), 0);
    k_zero<<<(BH_ * T_ + 255) / 256, 256>>>();

    dim3 g1(T_ / 64, BH_);
    k_dists<<<g1, 256>>>(qk, means);

    k_topk<<<BH_ * C_, 512>>>();

    cudaFuncSetAttribute(k_attn, cudaFuncAttributeMaxDynamicSharedMemorySize, SMEM_ATTN_BYTES);
    k_attn<<<BH_ * C_, NT_ATTN, SMEM_ATTN_BYTES>>>(qk, v, relw, out);

    int nf4 = BH_ * T_ * D_ / 4;
    k_norm<<<nf4 / 256, 256>>>(out, out_size > BH_ * T_ * D_ ? 1 : 0);
}